// round 5
// baseline (speedup 1.0000x reference)
#include <cuda_runtime.h>
#include <cuda_fp16.h>
#include <cstdint>

#define Hd     1536
#define FOURH  6144
#define NS     1008      // (T-1)*B = 63*16 sequential steps
#define CHUNKS 6         // 1536 / 256
#define CHALF  1024      // halves per chunk block (2 KB)
#define SC     3         // chunks cached in smem per warp

// ---------------- static device scratch ----------------
__device__ float  g_xpre[(size_t)NS * FOURH];                  // layer-0 input projection
__device__ __align__(16) __half g_Wp[3ULL * Hd * CHUNKS * CHALF]; // packed fp16 weights
__device__ float  g_h0[2][Hd];
__device__ float  g_h1[2][Hd];
__device__ float  g_pa[2][FOURH];
__device__ unsigned int g_bar_count = 0;
__device__ unsigned int g_bar_gen   = 0;

// dynamic smem: [ sh0: 1536 f32 | sh1: 1536 f32 | wcache: 32 warps * SC * CHALF halves ]
#define SMEM_BYTES (2 * Hd * 4 + 32 * SC * CHALF * 2)

// ---------------- software grid barrier ----------------
__device__ __forceinline__ void grid_barrier(int G) {
    __syncthreads();
    if (threadIdx.x == 0) {
        __threadfence();
        volatile unsigned int* genp = &g_bar_gen;
        unsigned int gen = *genp;
        unsigned int a = atomicAdd(&g_bar_count, 1u);
        if (a == (unsigned int)(G - 1)) {
            atomicExch(&g_bar_count, 0u);
            __threadfence();
            *genp = gen + 1u;
        } else {
            while (*genp == gen) { }
        }
    }
    __syncthreads();
}

// packed f32x2 FMA:  acc += w * (h, h)
__device__ __forceinline__ void ffma2(float2& acc, float2 w, float h) {
    asm("{\n\t"
        ".reg .b64 a, b, c;\n\t"
        "mov.b64 a, {%2, %3};\n\t"
        "mov.b64 b, {%4, %4};\n\t"
        "mov.b64 c, {%0, %1};\n\t"
        "fma.rn.f32x2 c, a, b, c;\n\t"
        "mov.b64 {%0, %1}, c;\n\t"
        "}" : "+f"(acc.x), "+f"(acc.y) : "f"(w.x), "f"(w.y), "f"(h));
}

__device__ __forceinline__ float2 wred2(float2 v) {
#pragma unroll
    for (int m = 16; m; m >>= 1) {
        double d;
        {
            double s = *(double*)&v;
            d = __shfl_xor_sync(0xffffffffu, s, m);
        }
        float2 o = *(float2*)&d;
        v.x += o.x; v.y += o.y;
    }
    return v;
}

__device__ __forceinline__ float sigm(float x) { return 1.0f / (1.0f + expf(-x)); }

// ---------------- weight conversion fp32 -> packed fp16 ----------------
// Per (mat, j, cc): block of 1024 halves. Within block: lane*32 + [0..15]=IF pairs
// (e-th pair = (w_i[k], w_f[k])), [16..31]=GO pairs, with k = cc*256 + e*32 + lane.
__global__ void convert_weights(const float* __restrict__ Whh0,
                                const float* __restrict__ Wih1,
                                const float* __restrict__ Whh1) {
    size_t idx = (size_t)blockIdx.x * blockDim.x + threadIdx.x;   // one per half2
    const size_t totalPairs = 3ULL * Hd * CHUNKS * (CHALF / 2);
    if (idx >= totalPairs) return;
    int p = (int)(idx & 511);           // pair within chunk block
    size_t cb = idx >> 9;               // chunk block index
    size_t rest = cb;
    int cc = (int)(rest % CHUNKS); rest /= CHUNKS;
    int j  = (int)(rest % Hd);
    int mat = (int)(rest / Hd);
    int lane = p >> 4;
    int sub  = p & 15;
    bool isGO = sub >= 8;
    int e = sub & 7;
    int k = cc * 256 + e * 32 + lane;
    const float* W = (mat == 0) ? Whh0 : (mat == 1) ? Wih1 : Whh1;
    int g0 = isGO ? 2 : 0, g1 = isGO ? 3 : 1;
    float a = W[(size_t)(g0 * Hd + j) * Hd + k];
    float b = W[(size_t)(g1 * Hd + j) * Hd + k];
    ((__half2*)g_Wp)[cb * 512 + p] = __floats2half2_rn(a, b);
}

// ---------------- Kernel: x_pre0 GEMM ----------------
__global__ void gemm_xpre(const float* __restrict__ batch,
                          const float* __restrict__ Wih0,
                          const float* __restrict__ bih0,
                          const float* __restrict__ bhh0) {
    const int BM = 64, BN = 64, BK = 32;
    __shared__ float Xs[BM][BK + 1];
    __shared__ float Ws[BN][BK + 1];

    int tid = threadIdx.x;
    int nb = blockIdx.x * BN;
    int mb = blockIdx.y * BM;
    int tx = tid % 16, ty = tid / 16;

    float acc[4][4];
#pragma unroll
    for (int i = 0; i < 4; i++)
#pragma unroll
        for (int jj = 0; jj < 4; jj++) acc[i][jj] = 0.0f;

    for (int k0 = 0; k0 < 256; k0 += BK) {
#pragma unroll
        for (int i = 0; i < 8; i++) {
            int idx = tid + i * 256;
            int r = idx >> 5, kk = idx & 31;
            int m = mb + r;
            float v = 0.0f;
            if (m < NS) {
                int ei = m >> 4, bb = m & 15;
                v = batch[(size_t)bb * (64 * 256) + (size_t)(ei + 1) * 256 + (k0 + kk)];
            }
            Xs[r][kk] = v;
        }
#pragma unroll
        for (int i = 0; i < 8; i++) {
            int idx = tid + i * 256;
            int r = idx >> 5, kk = idx & 31;
            Ws[r][kk] = Wih0[(size_t)(nb + r) * 256 + (k0 + kk)];
        }
        __syncthreads();
#pragma unroll
        for (int kk = 0; kk < BK; kk++) {
            float xv[4], wv[4];
#pragma unroll
            for (int i = 0; i < 4; i++) xv[i] = Xs[ty * 4 + i][kk];
#pragma unroll
            for (int jj = 0; jj < 4; jj++) wv[jj] = Ws[tx * 4 + jj][kk];
#pragma unroll
            for (int i = 0; i < 4; i++)
#pragma unroll
                for (int jj = 0; jj < 4; jj++) acc[i][jj] += xv[i] * wv[jj];
        }
        __syncthreads();
    }
#pragma unroll
    for (int i = 0; i < 4; i++) {
        int m = mb + ty * 4 + i;
        if (m >= NS) continue;
#pragma unroll
        for (int jj = 0; jj < 4; jj++) {
            int n = nb + tx * 4 + jj;
            g_xpre[(size_t)m * FOURH + n] = acc[i][jj] + bih0[n] + bhh0[n];
        }
    }
}

// ---------------- one 256-wide chunk of the 4-row matvec ----------------
template <typename HP>
__device__ __forceinline__ void mv_chunk(const HP* cp, const float* __restrict__ sh,
                                         int kbase, int lane,
                                         float2& aIF, float2& aGO) {
    const uint4* q = (const uint4*)(cp + lane * 32);
    uint4 uIF0 = q[0];
    uint4 uIF1 = q[1];
    uint4 uGO0 = q[2];
    uint4 uGO1 = q[3];
    float hv[8];
#pragma unroll
    for (int e = 0; e < 8; e++) hv[e] = sh[kbase + e * 32 + lane];
    const __half2* hIF0 = (const __half2*)&uIF0;
    const __half2* hIF1 = (const __half2*)&uIF1;
    const __half2* hGO0 = (const __half2*)&uGO0;
    const __half2* hGO1 = (const __half2*)&uGO1;
#pragma unroll
    for (int e = 0; e < 4; e++) {
        ffma2(aIF, __half22float2(hIF0[e]), hv[e]);
        ffma2(aGO, __half22float2(hGO0[e]), hv[e]);
    }
#pragma unroll
    for (int e = 0; e < 4; e++) {
        ffma2(aIF, __half22float2(hIF1[e]), hv[e + 4]);
        ffma2(aGO, __half22float2(hGO1[e]), hv[e + 4]);
    }
}

// ---------------- persistent sequential LSTM ----------------
__global__ __launch_bounds__(1024, 1)
void lstm_seq(const float* __restrict__ bih1,
              const float* __restrict__ bhh1,
              float* __restrict__ out,
              int G) {
    extern __shared__ unsigned char dynsmem[];
    float*  sh0    = (float*)dynsmem;               // 1536 f32
    float*  sh1    = sh0 + Hd;                      // 1536 f32
    __half* wcache = (__half*)(sh1 + Hd);           // 32 * SC * CHALF halves

    int tid  = threadIdx.x;
    int b    = blockIdx.x;
    int warp = tid >> 5;
    int lane = tid & 31;

    for (int i = tid; i < Hd; i += 1024) {
        g_h0[0][i] = 0.0f; g_h0[1][i] = 0.0f;
        g_h1[0][i] = 0.0f; g_h1[1][i] = 0.0f;
    }
    for (int i = tid + b * 1024; i < FOURH; i += 1024 * G) {
        g_pa[0][i] = 0.0f; g_pa[1][i] = 0.0f;
    }

    int u = warp * G + b;
    bool isL0 = (u < Hd);
    bool isA  = (u >= Hd)     && (u < 2 * Hd);
    bool isB  = (u >= 2 * Hd) && (u < 3 * Hd);
    int mat = isL0 ? 0 : isA ? 1 : 2;
    int j = isL0 ? u : isA ? (u - Hd) : (u - 2 * Hd);
    bool active = isL0 || isA || isB;

    const __half* gbase = g_Wp + ((size_t)(mat * Hd + j)) * CHUNKS * CHALF;
    __half* scache = wcache + (size_t)warp * SC * CHALF;

    // fill smem weight cache (chunks 0..SC-1), per-warp
    if (active) {
#pragma unroll
        for (int cc = 0; cc < SC; cc++) {
            const uint4* s = (const uint4*)(gbase + cc * CHALF + lane * 32);
            uint4* d = (uint4*)(scache + cc * CHALF + lane * 32);
            d[0] = s[0]; d[1] = s[1]; d[2] = s[2]; d[3] = s[3];
        }
    }

    float bi = 0.f, bf = 0.f, bg = 0.f, bo = 0.f;
    if (isB) {
        bi = bih1[0 * Hd + j] + bhh1[0 * Hd + j];
        bf = bih1[1 * Hd + j] + bhh1[1 * Hd + j];
        bg = bih1[2 * Hd + j] + bhh1[2 * Hd + j];
        bo = bih1[3 * Hd + j] + bhh1[3 * Hd + j];
    }

    grid_barrier(G);

    float c = 0.0f, h = 0.0f;   // register-resident cell state

    for (int it = 0; it <= NS + 1; ++it) {
        int rp = (it + 1) & 1;   // read parity
        int wp = it & 1;         // write parity

        {
            volatile const float* vh0 = g_h0[rp];
            volatile const float* vh1 = g_h1[rp];
            for (int i = tid; i < Hd; i += 1024) {
                sh0[i] = vh0[i];
                sh1[i] = vh1[i];
            }
        }
        __syncthreads();

        if (isL0) {
            if (it < NS) {
                float2 aIF = {0.f, 0.f}, aGO = {0.f, 0.f};
#pragma unroll
                for (int cc = 0; cc < SC; cc++)
                    mv_chunk(scache + cc * CHALF, sh0, cc * 256, lane, aIF, aGO);
#pragma unroll
                for (int cc = SC; cc < CHUNKS; cc++)
                    mv_chunk(gbase + cc * CHALF, sh0, cc * 256, lane, aIF, aGO);
                aIF = wred2(aIF); aGO = wred2(aGO);
                const float* xp = g_xpre + (size_t)it * FOURH;
                float pi = aIF.x + xp[0 * Hd + j];
                float pf = aIF.y + xp[1 * Hd + j];
                float pg = aGO.x + xp[2 * Hd + j];
                float po = aGO.y + xp[3 * Hd + j];
                c = sigm(pf) * c + sigm(pi) * tanhf(pg);
                h = sigm(po) * tanhf(c);
                if (lane == 0) ((volatile float*)g_h0[wp])[j] = h;
            }
        } else if (isA) {
            if (it >= 1 && it <= NS) {
                float2 aIF = {0.f, 0.f}, aGO = {0.f, 0.f};
#pragma unroll
                for (int cc = 0; cc < SC; cc++)
                    mv_chunk(scache + cc * CHALF, sh0, cc * 256, lane, aIF, aGO);
#pragma unroll
                for (int cc = SC; cc < CHUNKS; cc++)
                    mv_chunk(gbase + cc * CHALF, sh0, cc * 256, lane, aIF, aGO);
                aIF = wred2(aIF); aGO = wred2(aGO);
                if (lane == 0) {
                    volatile float* pa = g_pa[wp];
                    pa[0 * Hd + j] = aIF.x;
                    pa[1 * Hd + j] = aIF.y;
                    pa[2 * Hd + j] = aGO.x;
                    pa[3 * Hd + j] = aGO.y;
                }
            }
        } else if (isB) {
            if (it >= 2) {
                float2 aIF = {0.f, 0.f}, aGO = {0.f, 0.f};
#pragma unroll
                for (int cc = 0; cc < SC; cc++)
                    mv_chunk(scache + cc * CHALF, sh1, cc * 256, lane, aIF, aGO);
#pragma unroll
                for (int cc = SC; cc < CHUNKS; cc++)
                    mv_chunk(gbase + cc * CHALF, sh1, cc * 256, lane, aIF, aGO);
                aIF = wred2(aIF); aGO = wred2(aGO);
                if (lane == 0) {
                    volatile const float* pa = g_pa[rp];   // written at it-1
                    float pi = aIF.x + pa[0 * Hd + j] + bi;
                    float pf = aIF.y + pa[1 * Hd + j] + bf;
                    float pg = aGO.x + pa[2 * Hd + j] + bg;
                    float po = aGO.y + pa[3 * Hd + j] + bo;
                    c = sigm(pf) * c + sigm(pi) * tanhf(pg);
                    h = sigm(po) * tanhf(c);
                    ((volatile float*)g_h1[wp])[j] = h;
                }
            }
        }

        __threadfence();
        grid_barrier(G);
    }

    // out layout: [h0 | h1 | c0 | c1]
    if (lane == 0) {
        if (isL0) { out[j] = h;      out[2 * Hd + j] = c; }
        if (isB)  { out[Hd + j] = h; out[3 * Hd + j] = c; }
    }
}

// ---------------- launch ----------------
extern "C" void kernel_launch(void* const* d_in, const int* in_sizes, int n_in,
                              void* d_out, int out_size) {
    const float* batch = (const float*)d_in[0];
    const float* Wih0  = (const float*)d_in[1];
    const float* Whh0  = (const float*)d_in[2];
    const float* bih0  = (const float*)d_in[3];
    const float* bhh0  = (const float*)d_in[4];
    const float* Wih1  = (const float*)d_in[5];
    const float* Whh1  = (const float*)d_in[6];
    const float* bih1  = (const float*)d_in[7];
    const float* bhh1  = (const float*)d_in[8];
    float* out = (float*)d_out;

    int dev = 0;
    cudaGetDevice(&dev);
    int G = 0;
    cudaDeviceGetAttribute(&G, cudaDevAttrMultiProcessorCount, dev);
    if (G <= 0) G = 148;

    static int smem_set = 0;
    if (!smem_set) {
        cudaFuncSetAttribute(lstm_seq, cudaFuncAttributeMaxDynamicSharedMemorySize,
                             SMEM_BYTES);
        smem_set = 1;
    }

    size_t totalPairs = 3ULL * Hd * CHUNKS * (CHALF / 2);
    int cvt_blocks = (int)((totalPairs + 255) / 256);
    convert_weights<<<cvt_blocks, 256>>>(Whh0, Wih1, Whh1);

    dim3 g1(FOURH / 64, (NS + 63) / 64);
    gemm_xpre<<<g1, 256>>>(batch, Wih0, bih0, bhh0);

    lstm_seq<<<G, 1024, SMEM_BYTES>>>(bih1, bhh1, out, G);
}

// round 6
// speedup vs baseline: 1.7097x; 1.7097x over previous
#include <cuda_runtime.h>
#include <cuda_fp16.h>
#include <cstdint>

#define Hd     1536
#define FOURH  6144
#define NS     1008      // (T-1)*B = 63*16 sequential steps
#define CHUNKS 6         // 1536 / 256
#define SC     3         // chunks cached in smem per warp

// ---------------- static device scratch ----------------
__device__ float  g_xpre[(size_t)NS * FOURH];       // layer-0 input projection
__device__ __align__(16) __half g_Whh0h[(size_t)FOURH * Hd];  // fp16, lane-permuted
__device__ __align__(16) __half g_Wih1h[(size_t)FOURH * Hd];
__device__ __align__(16) __half g_Whh1h[(size_t)FOURH * Hd];
__device__ float  g_h0[2][Hd];
__device__ float  g_h1[2][Hd];
__device__ float  g_pa[2][FOURH];
__device__ unsigned int g_bar_count = 0;
__device__ unsigned int g_bar_gen   = 0;

// dyn smem: [ sh0:1536 f32 | sh1:1536 f32 | wcache: 32 warps * SC*4*256 halves (6KB/warp) ]
#define WC_PER_WARP (SC * 4 * 256)                 // halves
#define SMEM_BYTES  (2 * Hd * 4 + 32 * WC_PER_WARP * 2)

// ---------------- software grid barrier ----------------
__device__ __forceinline__ void grid_barrier(int G) {
    __syncthreads();
    if (threadIdx.x == 0) {
        __threadfence();
        volatile unsigned int* genp = &g_bar_gen;
        unsigned int gen = *genp;
        unsigned int a = atomicAdd(&g_bar_count, 1u);
        if (a == (unsigned int)(G - 1)) {
            atomicExch(&g_bar_count, 0u);
            __threadfence();
            *genp = gen + 1u;
        } else {
            while (*genp == gen) { }
        }
    }
    __syncthreads();
}

__device__ __forceinline__ float wred(float v) {
    v += __shfl_xor_sync(0xffffffffu, v, 16);
    v += __shfl_xor_sync(0xffffffffu, v, 8);
    v += __shfl_xor_sync(0xffffffffu, v, 4);
    v += __shfl_xor_sync(0xffffffffu, v, 2);
    v += __shfl_xor_sync(0xffffffffu, v, 1);
    return v;
}

__device__ __forceinline__ float sigm(float x) { return 1.0f / (1.0f + expf(-x)); }

// ---------------- weight conversion fp32 -> fp16 (lane-permuted, as R3) ----------------
// Within each 1536-wide row, dst position p = chunk*256 + lane*8 + e holds
// src element chunk*256 + e*32 + lane.
__global__ void convert_weights(const float* __restrict__ Whh0,
                                const float* __restrict__ Wih1,
                                const float* __restrict__ Whh1) {
    size_t idx = (size_t)blockIdx.x * blockDim.x + threadIdx.x;
    const size_t per = (size_t)FOURH * Hd;
    if (idx >= 3 * per) return;
    int which = (int)(idx / per);
    size_t rem = idx % per;
    size_t r = rem / Hd;
    int p = (int)(rem % Hd);
    int chunk = p >> 8, q = p & 255, lane = q >> 3, e = q & 7;
    int srcp = chunk * 256 + e * 32 + lane;
    const float* src = (which == 0) ? Whh0 : (which == 1) ? Wih1 : Whh1;
    __half* dst = (which == 0) ? g_Whh0h : (which == 1) ? g_Wih1h : g_Whh1h;
    dst[r * Hd + p] = __float2half(src[r * Hd + srcp]);
}

// ---------------- Kernel: x_pre0 GEMM (unchanged) ----------------
__global__ void gemm_xpre(const float* __restrict__ batch,
                          const float* __restrict__ Wih0,
                          const float* __restrict__ bih0,
                          const float* __restrict__ bhh0) {
    const int BM = 64, BN = 64, BK = 32;
    __shared__ float Xs[BM][BK + 1];
    __shared__ float Ws[BN][BK + 1];

    int tid = threadIdx.x;
    int nb = blockIdx.x * BN;
    int mb = blockIdx.y * BM;
    int tx = tid % 16, ty = tid / 16;

    float acc[4][4];
#pragma unroll
    for (int i = 0; i < 4; i++)
#pragma unroll
        for (int jj = 0; jj < 4; jj++) acc[i][jj] = 0.0f;

    for (int k0 = 0; k0 < 256; k0 += BK) {
#pragma unroll
        for (int i = 0; i < 8; i++) {
            int idx = tid + i * 256;
            int r = idx >> 5, kk = idx & 31;
            int m = mb + r;
            float v = 0.0f;
            if (m < NS) {
                int ei = m >> 4, bb = m & 15;
                v = batch[(size_t)bb * (64 * 256) + (size_t)(ei + 1) * 256 + (k0 + kk)];
            }
            Xs[r][kk] = v;
        }
#pragma unroll
        for (int i = 0; i < 8; i++) {
            int idx = tid + i * 256;
            int r = idx >> 5, kk = idx & 31;
            Ws[r][kk] = Wih0[(size_t)(nb + r) * 256 + (k0 + kk)];
        }
        __syncthreads();
#pragma unroll
        for (int kk = 0; kk < BK; kk++) {
            float xv[4], wv[4];
#pragma unroll
            for (int i = 0; i < 4; i++) xv[i] = Xs[ty * 4 + i][kk];
#pragma unroll
            for (int jj = 0; jj < 4; jj++) wv[jj] = Ws[tx * 4 + jj][kk];
#pragma unroll
            for (int i = 0; i < 4; i++)
#pragma unroll
                for (int jj = 0; jj < 4; jj++) acc[i][jj] += xv[i] * wv[jj];
        }
        __syncthreads();
    }
#pragma unroll
    for (int i = 0; i < 4; i++) {
        int m = mb + ty * 4 + i;
        if (m >= NS) continue;
#pragma unroll
        for (int jj = 0; jj < 4; jj++) {
            int n = nb + tx * 4 + jj;
            g_xpre[(size_t)m * FOURH + n] = acc[i][jj] + bih0[n] + bhh0[n];
        }
    }
}

// ---------------- one 256-wide chunk: 4 gate rows, generic pointers ----------------
// gp[t] points at the 256-half segment for gate t of this chunk (global or smem).
// Lane's uint4 at gp[t] + lane*8 : contiguous 512B per segment -> conflict-free LDS.
__device__ __forceinline__ void mv_chunk4(const __half* p0, const __half* p1,
                                          const __half* p2, const __half* p3,
                                          const float* __restrict__ sh, int kbase,
                                          int lane, float acc[4]) {
    float hv0 = sh[kbase + lane +   0], hv1 = sh[kbase + lane +  32];
    float hv2 = sh[kbase + lane +  64], hv3 = sh[kbase + lane +  96];
    float hv4 = sh[kbase + lane + 128], hv5 = sh[kbase + lane + 160];
    float hv6 = sh[kbase + lane + 192], hv7 = sh[kbase + lane + 224];
#pragma unroll
    for (int t = 0; t < 4; t++) {
        const __half* rp = (t == 0) ? p0 : (t == 1) ? p1 : (t == 2) ? p2 : p3;
        uint4 u = *(const uint4*)(rp + lane * 8);
        const __half2* h2 = (const __half2*)&u;
        float2 f0 = __half22float2(h2[0]);
        float2 f1 = __half22float2(h2[1]);
        float2 f2 = __half22float2(h2[2]);
        float2 f3 = __half22float2(h2[3]);
        acc[t] += f0.x * hv0 + f0.y * hv1 + f1.x * hv2 + f1.y * hv3
                + f2.x * hv4 + f2.y * hv5 + f3.x * hv6 + f3.y * hv7;
    }
}

// full 1536-wide 4-row matvec: chunks 0..SC-1 from smem cache, SC..5 from L2
__device__ __forceinline__ void mv4_hybrid(const __half* __restrict__ scache,
                                           const __half* __restrict__ gW, int j,
                                           const float* __restrict__ sh, int lane,
                                           float acc[4]) {
    const __half* r0 = gW + (size_t)(0 * Hd + j) * Hd;
    const __half* r1 = gW + (size_t)(1 * Hd + j) * Hd;
    const __half* r2 = gW + (size_t)(2 * Hd + j) * Hd;
    const __half* r3 = gW + (size_t)(3 * Hd + j) * Hd;
#pragma unroll
    for (int cc = 0; cc < SC; cc++) {
        const __half* base = scache + cc * 4 * 256;
        mv_chunk4(base + 0 * 256, base + 1 * 256, base + 2 * 256, base + 3 * 256,
                  sh, cc * 256, lane, acc);
    }
#pragma unroll
    for (int cc = SC; cc < CHUNKS; cc++) {
        mv_chunk4(r0 + cc * 256, r1 + cc * 256, r2 + cc * 256, r3 + cc * 256,
                  sh, cc * 256, lane, acc);
    }
}

// ---------------- persistent sequential LSTM ----------------
// Iteration it:
//   L0 warps: h0(it) from h0(it-1)                         [it < NS]
//   A  warps: pa(it-1) = Wih1 . h0(it-1)                   [1 <= it <= NS]
//   B  warps: finalize step it-2: Whh1 . h1(it-3) + pa     [it >= 2]
__global__ __launch_bounds__(1024, 1)
void lstm_seq(const float* __restrict__ bih1,
              const float* __restrict__ bhh1,
              float* __restrict__ out,
              int G) {
    extern __shared__ unsigned char dynsmem[];
    float*  sh0    = (float*)dynsmem;               // 1536 f32
    float*  sh1    = sh0 + Hd;                      // 1536 f32
    __half* wcache = (__half*)(sh1 + Hd);           // 32 * WC_PER_WARP halves

    int tid  = threadIdx.x;
    int b    = blockIdx.x;
    int warp = tid >> 5;
    int lane = tid & 31;

    for (int i = tid; i < Hd; i += 1024) {
        g_h0[0][i] = 0.0f; g_h0[1][i] = 0.0f;
        g_h1[0][i] = 0.0f; g_h1[1][i] = 0.0f;
    }
    for (int i = tid + b * 1024; i < FOURH; i += 1024 * G) {
        g_pa[0][i] = 0.0f; g_pa[1][i] = 0.0f;
    }

    int u = warp * G + b;
    bool isL0 = (u < Hd);
    bool isA  = (u >= Hd)     && (u < 2 * Hd);
    bool isB  = (u >= 2 * Hd) && (u < 3 * Hd);
    bool active = isL0 || isA || isB;
    int j = isL0 ? u : isA ? (u - Hd) : (u - 2 * Hd);

    const __half* gW = isL0 ? g_Whh0h : isA ? g_Wih1h : g_Whh1h;
    __half* scache = wcache + (size_t)warp * WC_PER_WARP;

    // fill per-warp smem cache: chunks 0..SC-1, 4 gate segments each (conflict-free layout)
    if (active) {
#pragma unroll
        for (int cc = 0; cc < SC; cc++) {
#pragma unroll
            for (int t = 0; t < 4; t++) {
                const __half* src = gW + (size_t)(t * Hd + j) * Hd + cc * 256 + lane * 8;
                __half* dst = scache + (cc * 4 + t) * 256 + lane * 8;
                *(uint4*)dst = *(const uint4*)src;
            }
        }
    }

    float bi = 0.f, bf = 0.f, bg = 0.f, bo = 0.f;
    if (isB) {
        bi = bih1[0 * Hd + j] + bhh1[0 * Hd + j];
        bf = bih1[1 * Hd + j] + bhh1[1 * Hd + j];
        bg = bih1[2 * Hd + j] + bhh1[2 * Hd + j];
        bo = bih1[3 * Hd + j] + bhh1[3 * Hd + j];
    }

    grid_barrier(G);

    float c = 0.0f, h = 0.0f;   // register-resident cell state

    for (int it = 0; it <= NS + 1; ++it) {
        int rp = (it + 1) & 1;   // read parity
        int wp = it & 1;         // write parity

        {
            volatile const float* vh0 = g_h0[rp];
            volatile const float* vh1 = g_h1[rp];
            for (int i = tid; i < Hd; i += 1024) {
                sh0[i] = vh0[i];
                sh1[i] = vh1[i];
            }
        }
        __syncthreads();

        if (isL0) {
            if (it < NS) {
                float acc[4] = {0.f, 0.f, 0.f, 0.f};
                mv4_hybrid(scache, gW, j, sh0, lane, acc);
                float pi = wred(acc[0]);
                float pf = wred(acc[1]);
                float pg = wred(acc[2]);
                float po = wred(acc[3]);
                const float* xp = g_xpre + (size_t)it * FOURH;
                pi += xp[0 * Hd + j];
                pf += xp[1 * Hd + j];
                pg += xp[2 * Hd + j];
                po += xp[3 * Hd + j];
                c = sigm(pf) * c + sigm(pi) * tanhf(pg);
                h = sigm(po) * tanhf(c);
                if (lane == 0) ((volatile float*)g_h0[wp])[j] = h;
            }
        } else if (isA) {
            if (it >= 1 && it <= NS) {
                float acc[4] = {0.f, 0.f, 0.f, 0.f};
                mv4_hybrid(scache, gW, j, sh0, lane, acc);
                float pi = wred(acc[0]);
                float pf = wred(acc[1]);
                float pg = wred(acc[2]);
                float po = wred(acc[3]);
                if (lane == 0) {
                    volatile float* pa = g_pa[wp];
                    pa[0 * Hd + j] = pi;
                    pa[1 * Hd + j] = pf;
                    pa[2 * Hd + j] = pg;
                    pa[3 * Hd + j] = po;
                }
            }
        } else if (isB) {
            if (it >= 2) {
                float acc[4] = {0.f, 0.f, 0.f, 0.f};
                mv4_hybrid(scache, gW, j, sh1, lane, acc);
                float pi = wred(acc[0]);
                float pf = wred(acc[1]);
                float pg = wred(acc[2]);
                float po = wred(acc[3]);
                if (lane == 0) {
                    volatile const float* pa = g_pa[rp];   // written at it-1
                    pi += pa[0 * Hd + j] + bi;
                    pf += pa[1 * Hd + j] + bf;
                    pg += pa[2 * Hd + j] + bg;
                    po += pa[3 * Hd + j] + bo;
                    c = sigm(pf) * c + sigm(pi) * tanhf(pg);
                    h = sigm(po) * tanhf(c);
                    ((volatile float*)g_h1[wp])[j] = h;
                }
            }
        }

        __threadfence();
        grid_barrier(G);
    }

    // out layout: [h0 | h1 | c0 | c1]
    if (lane == 0) {
        if (isL0) { out[j] = h;      out[2 * Hd + j] = c; }
        if (isB)  { out[Hd + j] = h; out[3 * Hd + j] = c; }
    }
}

// ---------------- launch ----------------
extern "C" void kernel_launch(void* const* d_in, const int* in_sizes, int n_in,
                              void* d_out, int out_size) {
    const float* batch = (const float*)d_in[0];
    const float* Wih0  = (const float*)d_in[1];
    const float* Whh0  = (const float*)d_in[2];
    const float* bih0  = (const float*)d_in[3];
    const float* bhh0  = (const float*)d_in[4];
    const float* Wih1  = (const float*)d_in[5];
    const float* Whh1  = (const float*)d_in[6];
    const float* bih1  = (const float*)d_in[7];
    const float* bhh1  = (const float*)d_in[8];
    float* out = (float*)d_out;

    int dev = 0;
    cudaGetDevice(&dev);
    int G = 0;
    cudaDeviceGetAttribute(&G, cudaDevAttrMultiProcessorCount, dev);
    if (G <= 0) G = 148;

    static int smem_set = 0;
    if (!smem_set) {
        cudaFuncSetAttribute(lstm_seq, cudaFuncAttributeMaxDynamicSharedMemorySize,
                             SMEM_BYTES);
        smem_set = 1;
    }

    size_t total = (size_t)3 * FOURH * Hd;
    int cvt_blocks = (int)((total + 255) / 256);
    convert_weights<<<cvt_blocks, 256>>>(Whh0, Wih1, Whh1);

    dim3 g1(FOURH / 64, (NS + 63) / 64);
    gemm_xpre<<<g1, 256>>>(batch, Wih0, bih0, bhh0);

    lstm_seq<<<G, 1024, SMEM_BYTES>>>(bih1, bhh1, out, G);
}